// round 6
// baseline (speedup 1.0000x reference)
#include <cuda_runtime.h>

// ---------------------------------------------------------------------------
// GATNet: 2-layer GAT, N=50000, E=800000 (+N self loops).
// R5 -> R6: CSR-by-dst counting sort + fused per-node gather aggregation
// (no feature atomics, softmax denom fused into the same loop),
// warp-per-node float2/float4 gathers, transposed weights for 4-wide
// GEMM loads, sigmoid/bias fused into layer-2 aggregation.
// ---------------------------------------------------------------------------

#define N_NODES 50000
#define F_IN    128
#define HID     64
#define C_OUT   121
#define C_PAD   128                        // hW2 row stride (32 float4)
#define E_RAW   800000
#define E_TOT   (E_RAW + N_NODES)          // CSR entries incl. self loops

// Scratch (static device globals -- allocation is forbidden)
__device__ int   g_edge[2 * E_RAW];                      // int32 src | dst
__device__ int   g_is32;
__device__ int   g_cnt [N_NODES];                        // counts, then cursors
__device__ int   g_rowptr[N_NODES + 1];
__device__ __align__(8)  int2  g_csr_sd[E_TOT];          // (src, dst) CSR order
__device__ __align__(8)  int2  g_csr_sw[E_TOT];          // (src, w-bits) CSR order
__device__ __align__(16) float g_h1   [N_NODES * HID];   // x @ W1
__device__ __align__(16) float g_hrelu[N_NODES * HID];   // relu(agg1 + b1)
__device__ __align__(16) float g_hW2  [N_NODES * C_PAD]; // hrelu @ W2 (padded)
__device__ float g_as[N_NODES];
__device__ float g_ad[N_NODES];
__device__ __align__(16) float g_W1t[HID * F_IN];        // W1 transposed [64][128]
__device__ __align__(16) float g_W2t[C_OUT * HID];       // W2 transposed [121][64]

// ---------------- dtype detection + index conversion -----------------------
__global__ void k_detect(const unsigned* __restrict__ ei32) {
    __shared__ int found;
    if (threadIdx.x == 0) found = 0;
    __syncthreads();
    int local = 0;
    for (int k = threadIdx.x; k < 4096; k += blockDim.x) {
        const int j = k * (E_RAW / 4096);
        if (ei32[2 * j + 1] != 0u) local = 1;
    }
    if (local) found = 1;
    __syncthreads();
    if (threadIdx.x == 0) g_is32 = found;
}

__global__ void k_convert(const void* __restrict__ ei) {
    const int i = blockIdx.x * blockDim.x + threadIdx.x;
    if (i >= 2 * E_RAW) return;
    g_edge[i] = g_is32 ? ((const int*)ei)[i]
                       : (int)((const long long*)ei)[i];
}

// ---------------- weight transposes ----------------------------------------
__global__ void k_wtrans(const float* __restrict__ W1,
                         const float* __restrict__ W2) {
    const int stride = gridDim.x * blockDim.x;
    const int i0 = blockIdx.x * blockDim.x + threadIdx.x;
    for (int t = i0; t < HID * F_IN; t += stride) {
        const int f = t / F_IN, k = t - f * F_IN;
        g_W1t[f * F_IN + k] = W1[k * HID + f];
    }
    for (int t = i0; t < C_OUT * HID; t += stride) {
        const int f = t / HID, k = t - f * HID;
        g_W2t[f * HID + k] = W2[k * C_OUT + f];
    }
}

// ---------------- CSR build -------------------------------------------------
__global__ void k_histinit() {
    const int i = blockIdx.x * blockDim.x + threadIdx.x;
    if (i < N_NODES) g_cnt[i] = 1;          // self-loop slot
}
__global__ void k_hist() {
    const int i = blockIdx.x * blockDim.x + threadIdx.x;
    if (i >= E_RAW) return;
    atomicAdd(&g_cnt[g_edge[E_RAW + i]], 1);
}

// exclusive scan of g_cnt -> g_rowptr, single block of 1024 threads
__global__ void k_scan() {
    __shared__ int woff[32];
    __shared__ int carry, chunk_total;
    const int t = threadIdx.x, lane = t & 31, wid = t >> 5;
    if (t == 0) carry = 0;
    __syncthreads();
    for (int base = 0; base < N_NODES; base += 1024) {
        const int i = base + t;
        const int v = (i < N_NODES) ? g_cnt[i] : 0;
        int incl = v;
#pragma unroll
        for (int off = 1; off < 32; off <<= 1) {
            int y = __shfl_up_sync(0xffffffffu, incl, off);
            if (lane >= off) incl += y;
        }
        if (lane == 31) woff[wid] = incl;
        __syncthreads();
        if (wid == 0) {
            int s = woff[lane];
            int si = s;
#pragma unroll
            for (int off = 1; off < 32; off <<= 1) {
                int y = __shfl_up_sync(0xffffffffu, si, off);
                if (lane >= off) si += y;
            }
            woff[lane] = si - s;
            if (lane == 31) chunk_total = si;
        }
        __syncthreads();
        if (i < N_NODES) g_rowptr[i] = carry + woff[wid] + incl - v;
        __syncthreads();
        if (t == 0) carry += chunk_total;
        __syncthreads();
    }
    if (t == 0) g_rowptr[N_NODES] = carry;   // == E_TOT
}

__global__ void k_selfcur() {
    const int n = blockIdx.x * blockDim.x + threadIdx.x;
    if (n >= N_NODES) return;
    g_csr_sd[g_rowptr[n]] = make_int2(n, n);   // self loop at slot 0
    g_cnt[n] = 1;                              // cursor
}
__global__ void k_fill() {
    const int i = blockIdx.x * blockDim.x + threadIdx.x;
    if (i >= E_RAW) return;
    const int s = g_edge[i];
    const int d = g_edge[E_RAW + i];
    const int p = g_rowptr[d] + atomicAdd(&g_cnt[d], 1);
    g_csr_sd[p] = make_int2(s, d);
}

// ---------------- GEMM 1: h1 = x @ W1, alpha_src/dst ------------------------
__global__ void k_gemm1(const float* __restrict__ x,
                        const float* __restrict__ a_src,
                        const float* __restrict__ a_dst) {
    __shared__ float4 xs4[F_IN / 4];
    __shared__ float r1[HID], r2[HID];
    const int node = blockIdx.x;
    const int f = threadIdx.x;  // 0..63
    if (f < F_IN / 4) xs4[f] = ((const float4*)x)[node * (F_IN / 4) + f];
    __syncthreads();
    const float4* w4 = (const float4*)(g_W1t + f * F_IN);
    float acc = 0.f;
#pragma unroll
    for (int j = 0; j < F_IN / 4; j++) {
        const float4 w = w4[j];
        const float4 v = xs4[j];
        acc += w.x * v.x + w.y * v.y + w.z * v.z + w.w * v.w;
    }
    g_h1[node * HID + f] = acc;
    r1[f] = acc * a_src[f];
    r2[f] = acc * a_dst[f];
    __syncthreads();
    for (int s = HID / 2; s > 0; s >>= 1) {
        if (f < s) { r1[f] += r1[f + s]; r2[f] += r2[f + s]; }
        __syncthreads();
    }
    if (f == 0) { g_as[node] = r1[0]; g_ad[node] = r2[0]; }
}

// ---------------- per-layer edge weights (CSR order, no atomics) ------------
__global__ void k_wpass() {
    const int i = blockIdx.x * blockDim.x + threadIdx.x;
    if (i >= E_TOT) return;
    const int2 sd = g_csr_sd[i];
    float e = g_as[sd.x] + g_ad[sd.y];
    e = (e > 0.f) ? e : 0.2f * e;             // leaky_relu 0.2
    g_csr_sw[i] = make_int2(sd.x, __float_as_int(__expf(e)));
}

// ---------------- fused aggregation, layer 1 (warp per node, float2) --------
// out: g_hrelu = relu( (sum_w w*h1[src]) / (sum_w) + b1 )
__global__ void k_agg1(const float* __restrict__ b1) {
    const int node = blockIdx.x * 2 + (threadIdx.x >> 5);
    const int lane = threadIdx.x & 31;
    const int beg = g_rowptr[node];
    const int end = g_rowptr[node + 1];
    float2 acc = make_float2(0.f, 0.f);
    float wsum = 0.f;
#pragma unroll 2
    for (int e = beg; e < end; e++) {
        const int2 sw = g_csr_sw[e];
        const float w = __int_as_float(sw.y);
        const float2 h = *(const float2*)(g_h1 + sw.x * HID + lane * 2);
        acc.x += w * h.x; acc.y += w * h.y; wsum += w;
    }
    const float inv = 1.f / wsum;
    const float2 b = *(const float2*)(b1 + lane * 2);
    float vx = acc.x * inv + b.x;
    float vy = acc.y * inv + b.y;
    vx = vx > 0.f ? vx : 0.f;
    vy = vy > 0.f ? vy : 0.f;
    ((float2*)g_hrelu)[node * (HID / 2) + lane] = make_float2(vx, vy);
}

// ---------------- GEMM 2: hW2 = hrelu @ W2 (padded), alpha2 -----------------
__global__ void k_gemm2(const float* __restrict__ a_src2,
                        const float* __restrict__ a_dst2) {
    __shared__ float4 hs4[HID / 4];
    __shared__ float r1[128], r2[128];
    const int node = blockIdx.x;
    const int f = threadIdx.x;  // 0..127
    if (f < HID / 4) hs4[f] = ((const float4*)g_hrelu)[node * (HID / 4) + f];
    __syncthreads();
    if (f < C_OUT) {
        const float4* w4 = (const float4*)(g_W2t + f * HID);
        float acc = 0.f;
#pragma unroll
        for (int j = 0; j < HID / 4; j++) {
            const float4 w = w4[j];
            const float4 v = hs4[j];
            acc += w.x * v.x + w.y * v.y + w.z * v.z + w.w * v.w;
        }
        g_hW2[node * C_PAD + f] = acc;
        r1[f] = acc * a_src2[f];
        r2[f] = acc * a_dst2[f];
    } else {
        g_hW2[node * C_PAD + f] = 0.f;        // zero padding cols 121..127
        r1[f] = 0.f; r2[f] = 0.f;
    }
    __syncthreads();
    for (int s = 64; s > 0; s >>= 1) {
        if (f < s) { r1[f] += r1[f + s]; r2[f] += r2[f + s]; }
        __syncthreads();
    }
    if (f == 0) { g_as[node] = r1[0]; g_ad[node] = r2[0]; }
}

// ---------------- fused aggregation, layer 2 (warp per node, float4) --------
// out[n,f] = sigmoid( (sum_w w*hW2[src,f]) / (sum_w) + b2[f] )
__global__ void k_agg2(float* __restrict__ out, const float* __restrict__ b2) {
    const int node = blockIdx.x * 4 + (threadIdx.x >> 5);
    const int lane = threadIdx.x & 31;
    const int beg = g_rowptr[node];
    const int end = g_rowptr[node + 1];
    float4 acc = make_float4(0.f, 0.f, 0.f, 0.f);
    float wsum = 0.f;
#pragma unroll 2
    for (int e = beg; e < end; e++) {
        const int2 sw = g_csr_sw[e];
        const float w = __int_as_float(sw.y);
        const float4 h = *(const float4*)(g_hW2 + sw.x * C_PAD + lane * 4);
        acc.x += w * h.x; acc.y += w * h.y;
        acc.z += w * h.z; acc.w += w * h.w;
        wsum += w;
    }
    const float inv = 1.f / wsum;
    const float a[4] = {acc.x, acc.y, acc.z, acc.w};
#pragma unroll
    for (int j = 0; j < 4; j++) {
        const int f = lane * 4 + j;
        if (f < C_OUT) {
            const float v = a[j] * inv + b2[f];
            out[node * C_OUT + f] = 1.f / (1.f + __expf(-v));
        }
    }
}

// ---------------------------------------------------------------------------
extern "C" void kernel_launch(void* const* d_in, const int* in_sizes, int n_in,
                              void* d_out, int out_size) {
    const float* x      = (const float*)d_in[0];
    const void*  ei     = d_in[1];
    const float* W1     = (const float*)d_in[2];
    const float* a_src1 = (const float*)d_in[3];
    const float* a_dst1 = (const float*)d_in[4];
    const float* b1     = (const float*)d_in[5];
    const float* W2     = (const float*)d_in[6];
    const float* a_src2 = (const float*)d_in[7];
    const float* a_dst2 = (const float*)d_in[8];
    const float* b2     = (const float*)d_in[9];
    float*       out    = (float*)d_out;

    const int TPB = 256;
    const int gN  = (N_NODES + TPB - 1) / TPB;
    const int gE  = (E_RAW + TPB - 1) / TPB;
    const int gET = (E_TOT + TPB - 1) / TPB;

    // ----- index conversion + CSR build + weight transpose -----
    k_detect<<<1, 256>>>((const unsigned*)ei);
    k_convert<<<(2 * E_RAW + TPB - 1) / TPB, TPB>>>(ei);
    k_wtrans<<<32, TPB>>>(W1, W2);
    k_histinit<<<gN, TPB>>>();
    k_hist<<<gE, TPB>>>();
    k_scan<<<1, 1024>>>();
    k_selfcur<<<gN, TPB>>>();
    k_fill<<<gE, TPB>>>();

    // ----- Layer 1 -----
    k_gemm1<<<N_NODES, HID>>>(x, a_src1, a_dst1);
    k_wpass<<<gET, TPB>>>();
    k_agg1<<<N_NODES / 2, 64>>>(b1);

    // ----- Layer 2 -----
    k_gemm2<<<N_NODES, 128>>>(a_src2, a_dst2);
    k_wpass<<<gET, TPB>>>();
    k_agg2<<<N_NODES / 4, 128>>>(out, b2);
}